// round 13
// baseline (speedup 1.0000x reference)
#include <cuda_runtime.h>
#include <math.h>
#include <stdint.h>

#define N_NODES 50000
#define N_EDGES 800000
#define DIM_IN 128
#define DIM 96
#define NUM_GRAPHS 64

// ---------------- scratch (device globals; zero-init at module load) ------
__device__ float g_h[N_NODES * DIM];     // post-GEMM features
__device__ float g_buf[N_NODES * DIM];   // post-aggregation layer output
__device__ float g_as[N_NODES];          // alpha_src per node
__device__ float g_ad[N_NODES];          // alpha_dst per node
__device__ int   g_deg[N_NODES];         // INVARIANT: zero before/after every call
__device__ int   g_row[N_NODES + 1];
__device__ int   g_cur[N_NODES];
__device__ int   g_csrc[N_EDGES];        // CSR (by dst) source ids, real edges only

// ---------------- CSR build (3 kernels; self-loops handled in k_agg) -------
__global__ void k_count(const int* __restrict__ ei) {
    int e = blockIdx.x * blockDim.x + threadIdx.x;
    if (e < N_EDGES) atomicAdd(&g_deg[ei[N_EDGES + e]], 1);
}

// single-block: exclusive scan of deg -> row, init cur=row, restore deg=0.
// (No scattered csrc stores here — that was the R6 merged-scan mistake.)
__global__ void k_scan() {
    __shared__ int partial[1024];
    const int t = threadIdx.x;
    const int CH = (N_NODES + 1023) / 1024;
    int b = t * CH;
    int e = min(b + CH, N_NODES);
    int s = 0;
    for (int i = b; i < e; i++) s += g_deg[i];
    partial[t] = s;
    __syncthreads();
    for (int off = 1; off < 1024; off <<= 1) {
        int add = (t >= off) ? partial[t - off] : 0;
        __syncthreads();
        partial[t] += add;
        __syncthreads();
    }
    int run = (t > 0) ? partial[t - 1] : 0;
    for (int i = b; i < e; i++) {
        int d = g_deg[i];
        g_deg[i] = 0;                 // restore zero invariant
        g_row[i] = run;
        g_cur[i] = run;
        run += d;
    }
    if (t == 1023) g_row[N_NODES] = partial[1023];
}

__global__ void k_scatter(const int* __restrict__ ei) {
    int e = blockIdx.x * blockDim.x + threadIdx.x;
    if (e < N_EDGES) {
        int d = ei[N_EDGES + e];
        int s = ei[e];
        int p = atomicAdd(&g_cur[d], 1);
        g_csrc[p] = s;
    }
}

// ---------------- tf32 tensor-core GEMM: H[M,96] = A[M,K] @ W[K,96] --------
__device__ __forceinline__ uint32_t f2tf(float f) {
    uint32_t r;
    asm("cvt.rna.tf32.f32 %0, %1;" : "=r"(r) : "f"(f));
    return r;
}

template <int K, bool FROMBUF>
__global__ void __launch_bounds__(256) k_gemm(const float* __restrict__ Ain,
                                              const float* __restrict__ W) {
    __shared__ uint32_t As[32][136];   // [k][m], pad -> conflict-free frags
    __shared__ uint32_t Bs[32][104];   // [k][n]
    const float* A = FROMBUF ? g_buf : Ain;
    const int tid  = threadIdx.x;
    const int lane = tid & 31;
    const int warp = tid >> 5;
    const int wm   = warp >> 1;        // 0..3
    const int wn   = warp & 1;         // 0..1
    const int gid  = lane >> 2;        // 0..7
    const int tig  = lane & 3;         // 0..3
    const int m0   = blockIdx.x * 128;
    const int NCH  = K / 32;

    float acc[2][6][4];
#pragma unroll
    for (int tm = 0; tm < 2; tm++)
#pragma unroll
        for (int tn = 0; tn < 6; tn++)
#pragma unroll
            for (int i = 0; i < 4; i++) acc[tm][tn][i] = 0.f;

    uint32_t pA[16], pB[12];
#pragma unroll
    for (int i = 0; i < 16; i++) {
        int idx = tid + i * 256;
        int k = idx & 31, m = idx >> 5;
        int row = m0 + m;
        pA[i] = f2tf((row < N_NODES) ? A[row * K + k] : 0.f);
    }
#pragma unroll
    for (int i = 0; i < 12; i++) {
        int idx = tid + i * 256;
        int c = idx % 96, k = idx / 96;
        pB[i] = f2tf(W[k * 96 + c]);
    }

#pragma unroll
    for (int ch = 0; ch < NCH; ch++) {
#pragma unroll
        for (int i = 0; i < 16; i++) {
            int idx = tid + i * 256;
            int k = idx & 31, m = idx >> 5;
            As[k][m] = pA[i];
        }
#pragma unroll
        for (int i = 0; i < 12; i++) {
            int idx = tid + i * 256;
            int c = idx % 96, k = idx / 96;
            Bs[k][c] = pB[i];
        }
        __syncthreads();

        if (ch + 1 < NCH) {
            int k0 = (ch + 1) * 32;
#pragma unroll
            for (int i = 0; i < 16; i++) {
                int idx = tid + i * 256;
                int k = idx & 31, m = idx >> 5;
                int row = m0 + m;
                pA[i] = f2tf((row < N_NODES) ? A[row * K + k0 + k] : 0.f);
            }
#pragma unroll
            for (int i = 0; i < 12; i++) {
                int idx = tid + i * 256;
                int c = idx % 96, k = idx / 96;
                pB[i] = f2tf(W[(k0 + k) * 96 + c]);
            }
        }

#pragma unroll
        for (int k8 = 0; k8 < 4; k8++) {
            const int kb = k8 * 8;
            uint32_t af[2][4];
#pragma unroll
            for (int tm = 0; tm < 2; tm++) {
                int mb = wm * 32 + tm * 16;
                af[tm][0] = As[kb + tig][mb + gid];
                af[tm][1] = As[kb + tig][mb + gid + 8];
                af[tm][2] = As[kb + tig + 4][mb + gid];
                af[tm][3] = As[kb + tig + 4][mb + gid + 8];
            }
            uint32_t bf[6][2];
#pragma unroll
            for (int tn = 0; tn < 6; tn++) {
                int nb = wn * 48 + tn * 8;
                bf[tn][0] = Bs[kb + tig][nb + gid];
                bf[tn][1] = Bs[kb + tig + 4][nb + gid];
            }
#pragma unroll
            for (int tm = 0; tm < 2; tm++)
#pragma unroll
                for (int tn = 0; tn < 6; tn++) {
                    asm volatile(
                        "mma.sync.aligned.m16n8k8.row.col.f32.tf32.tf32.f32 "
                        "{%0,%1,%2,%3}, {%4,%5,%6,%7}, {%8,%9}, {%0,%1,%2,%3};"
                        : "+f"(acc[tm][tn][0]), "+f"(acc[tm][tn][1]),
                          "+f"(acc[tm][tn][2]), "+f"(acc[tm][tn][3])
                        : "r"(af[tm][0]), "r"(af[tm][1]),
                          "r"(af[tm][2]), "r"(af[tm][3]),
                          "r"(bf[tn][0]), "r"(bf[tn][1]));
                }
        }
        __syncthreads();
    }

#pragma unroll
    for (int tm = 0; tm < 2; tm++) {
        int rbase = m0 + wm * 32 + tm * 16;
        int row0 = rbase + gid;
        int row1 = rbase + gid + 8;
#pragma unroll
        for (int tn = 0; tn < 6; tn++) {
            int col = wn * 48 + tn * 8 + 2 * tig;
            if (row0 < N_NODES) {
                float2 v = make_float2(acc[tm][tn][0], acc[tm][tn][1]);
                *(float2*)&g_h[row0 * 96 + col] = v;
            }
            if (row1 < N_NODES) {
                float2 v = make_float2(acc[tm][tn][2], acc[tm][tn][3]);
                *(float2*)&g_h[row1 * 96 + col] = v;
            }
        }
    }
}

// ---------------- per-node attention logits ----------------
__global__ void k_alpha(const float* __restrict__ asrc, const float* __restrict__ adst) {
    int warp = (blockIdx.x * blockDim.x + threadIdx.x) >> 5;
    int lane = threadIdx.x & 31;
    if (warp >= N_NODES) return;
    float s1 = 0.f, s2 = 0.f;
#pragma unroll
    for (int i = 0; i < 3; i++) {
        float v = g_h[warp * 96 + lane + 32 * i];
        s1 = fmaf(v, asrc[lane + 32 * i], s1);
        s2 = fmaf(v, adst[lane + 32 * i], s2);
    }
#pragma unroll
    for (int o = 16; o; o >>= 1) {
        s1 += __shfl_xor_sync(0xffffffffu, s1, o);
        s2 += __shfl_xor_sync(0xffffffffu, s2, o);
    }
    if (lane == 0) { g_as[warp] = s1; g_ad[warp] = s2; }
}

// ---------------- warp-per-dst softmax + aggregation ----------
// Self-loop handled in closed form (coalesced h[d] read), real edges gathered.
// No max pass: exp(e)/sum(exp(e)) exact; |e| bounded ~6 << 88.
__global__ void k_agg(const float* __restrict__ bias, int act) {
    int d    = (blockIdx.x * blockDim.x + threadIdx.x) >> 5;
    int lane = threadIdx.x & 31;
    if (d >= N_NODES) return;
    const int start = g_row[d];
    const int end   = g_row[d + 1];
    const float ad  = g_ad[d];

    // self-loop term
    float es = __ldg(&g_as[d]) + ad;
    es = es > 0.f ? es : 0.2f * es;
    const float wself = __expf(es);
    float a0 = wself * g_h[d * 96 + lane];
    float a1 = wself * g_h[d * 96 + lane + 32];
    float a2 = wself * g_h[d * 96 + lane + 64];

    float denom = 0.f;
    for (int base = start; base < end; base += 32) {
        int j = base + lane;
        int s = 0;
        float w = 0.f;
        if (j < end) {
            s = __ldg(&g_csrc[j]);
            float e = __ldg(&g_as[s]) + ad;
            e = e > 0.f ? e : 0.2f * e;
            w = __expf(e);
        }
        denom += w;
        const int cnt = min(32, end - base);
        int t = 0;
        for (; t + 2 <= cnt; t += 2) {
            float wt0 = __shfl_sync(0xffffffffu, w, t);
            int   st0 = __shfl_sync(0xffffffffu, s, t);
            float wt1 = __shfl_sync(0xffffffffu, w, t + 1);
            int   st1 = __shfl_sync(0xffffffffu, s, t + 1);
            const float* h0 = g_h + st0 * 96;
            const float* h1 = g_h + st1 * 96;
            float v00 = __ldg(h0 + lane), v01 = __ldg(h0 + lane + 32), v02 = __ldg(h0 + lane + 64);
            float v10 = __ldg(h1 + lane), v11 = __ldg(h1 + lane + 32), v12 = __ldg(h1 + lane + 64);
            a0 = fmaf(wt0, v00, a0); a1 = fmaf(wt0, v01, a1); a2 = fmaf(wt0, v02, a2);
            a0 = fmaf(wt1, v10, a0); a1 = fmaf(wt1, v11, a1); a2 = fmaf(wt1, v12, a2);
        }
        if (t < cnt) {
            float wt = __shfl_sync(0xffffffffu, w, t);
            int   st = __shfl_sync(0xffffffffu, s, t);
            const float* hp = g_h + st * 96;
            a0 = fmaf(wt, __ldg(hp + lane),      a0);
            a1 = fmaf(wt, __ldg(hp + lane + 32), a1);
            a2 = fmaf(wt, __ldg(hp + lane + 64), a2);
        }
    }
#pragma unroll
    for (int o = 16; o; o >>= 1) denom += __shfl_xor_sync(0xffffffffu, denom, o);
    float inv = 1.f / (denom + wself + 1e-16f);

    float o0 = a0 * inv + bias[lane];
    float o1 = a1 * inv + bias[lane + 32];
    float o2 = a2 * inv + bias[lane + 64];
    if (act) {
        o0 = o0 > 0.f ? o0 : 0.01f * o0;
        o1 = o1 > 0.f ? o1 : 0.01f * o1;
        o2 = o2 > 0.f ? o2 : 0.01f * o2;
    }
    g_buf[d * 96 + lane]      = o0;
    g_buf[d * 96 + lane + 32] = o1;
    g_buf[d * 96 + lane + 64] = o2;
}

// ---------------- global mean pool (batch is sorted, int32) ----------------
__global__ void k_pool(const int* __restrict__ batch, float* __restrict__ out) {
    int g = blockIdx.x;
    __shared__ int s_lo, s_hi;
    if (threadIdx.x == 0) {
        int l = 0, r = N_NODES;
        while (l < r) { int mid = (l + r) >> 1; if (batch[mid] < g) l = mid + 1; else r = mid; }
        s_lo = l;
        l = 0; r = N_NODES;
        while (l < r) { int mid = (l + r) >> 1; if (batch[mid] < g + 1) l = mid + 1; else r = mid; }
        s_hi = l;
    }
    __syncthreads();
    int t = threadIdx.x;   // 96 threads
    float s = 0.f;
    for (int n = s_lo; n < s_hi; n++) s += g_buf[n * 96 + t];
    int cnt = s_hi - s_lo;
    out[g * 96 + t] = s / (float)max(cnt, 1);
}

// ---------------- launch ----------------
extern "C" void kernel_launch(void* const* d_in, const int* in_sizes, int n_in,
                              void* d_out, int out_size) {
    const float* x     = (const float*)d_in[0];
    const int*   ei    = (const int*)d_in[1];    // int32 (JAX x64 disabled)
    const int*   batch = (const int*)d_in[2];    // int32
    const float* W1 = (const float*)d_in[3];
    const float* s1 = (const float*)d_in[4];
    const float* a1 = (const float*)d_in[5];
    const float* b1 = (const float*)d_in[6];
    const float* W2 = (const float*)d_in[7];
    const float* s2 = (const float*)d_in[8];
    const float* a2 = (const float*)d_in[9];
    const float* b2 = (const float*)d_in[10];
    const float* W3 = (const float*)d_in[11];
    const float* s3 = (const float*)d_in[12];
    const float* a3 = (const float*)d_in[13];
    const float* b3 = (const float*)d_in[14];
    float* out = (float*)d_out;

    // lazily-created side stream + fork/join events (host resources only)
    static cudaStream_t sB = nullptr;
    static cudaEvent_t evFork = nullptr, evJoin = nullptr;
    if (sB == nullptr) {
        cudaStreamCreateWithFlags(&sB, cudaStreamNonBlocking);
        cudaEventCreateWithFlags(&evFork, cudaEventDisableTiming);
        cudaEventCreateWithFlags(&evJoin, cudaEventDisableTiming);
    }

    // ---- fork: CSR build on side stream, layer-1 GEMM+alpha on main ----
    cudaEventRecord(evFork, 0);
    cudaStreamWaitEvent(sB, evFork, 0);

    k_count<<<(N_EDGES + 255) / 256, 256, 0, sB>>>(ei);
    k_scan<<<1, 1024, 0, sB>>>();
    k_scatter<<<(N_EDGES + 255) / 256, 256, 0, sB>>>(ei);
    cudaEventRecord(evJoin, sB);

    const int GEMM_GRID = (N_NODES + 127) / 128;
    const int WARP_GRID = (N_NODES * 32 + 255) / 256;

    k_gemm<DIM_IN, false><<<GEMM_GRID, 256>>>(x, W1);
    k_alpha<<<WARP_GRID, 256>>>(s1, a1);

    // ---- join: aggregation needs both CSR and alpha ----
    cudaStreamWaitEvent(0, evJoin, 0);
    k_agg<<<WARP_GRID, 256>>>(b1, 1);

    // layer 2
    k_gemm<DIM, true><<<GEMM_GRID, 256>>>(nullptr, W2);
    k_alpha<<<WARP_GRID, 256>>>(s2, a2);
    k_agg<<<WARP_GRID, 256>>>(b2, 1);
    // layer 3
    k_gemm<DIM, true><<<GEMM_GRID, 256>>>(nullptr, W3);
    k_alpha<<<WARP_GRID, 256>>>(s3, a3);
    k_agg<<<WARP_GRID, 256>>>(b3, 0);

    // pool
    k_pool<<<NUM_GRAPHS, 96>>>(batch, out);
}

// round 14
// speedup vs baseline: 1.2263x; 1.2263x over previous
#include <cuda_runtime.h>
#include <math.h>
#include <stdint.h>

#define N_NODES 50000
#define N_EDGES 800000
#define ETOT (N_EDGES + N_NODES)
#define DIM_IN 128
#define DIM 96
#define NUM_GRAPHS 64

// ---------------- scratch (device globals) ----------
__device__ float g_h[N_NODES * DIM];     // post-GEMM features
__device__ float g_buf[N_NODES * DIM];   // post-aggregation layer output
__device__ float g_as[N_NODES];          // alpha_src per node
__device__ float g_ad[N_NODES];          // alpha_dst per node
__device__ int   g_deg[N_NODES];
__device__ int   g_row[N_NODES + 1];
__device__ int   g_cur[N_NODES];
__device__ int   g_csrc[ETOT];           // CSR (by dst) source node ids

// ---------------- CSR build (5 small kernels — measured-fast structure) ----
__global__ void k_init_deg() {
    int i = blockIdx.x * blockDim.x + threadIdx.x;
    if (i < N_NODES) g_deg[i] = 1;   // self loop
}

__global__ void k_count(const int* __restrict__ ei) {
    int e = blockIdx.x * blockDim.x + threadIdx.x;
    if (e < N_EDGES) atomicAdd(&g_deg[ei[N_EDGES + e]], 1);
}

__global__ void k_scan() {
    __shared__ int partial[1024];
    const int t = threadIdx.x;
    const int CH = (N_NODES + 1023) / 1024;
    int b = t * CH;
    int e = min(b + CH, N_NODES);
    int s = 0;
    for (int i = b; i < e; i++) s += g_deg[i];
    partial[t] = s;
    __syncthreads();
    for (int off = 1; off < 1024; off <<= 1) {
        int add = (t >= off) ? partial[t - off] : 0;
        __syncthreads();
        partial[t] += add;
        __syncthreads();
    }
    int run = (t > 0) ? partial[t - 1] : 0;
    for (int i = b; i < e; i++) { g_row[i] = run; run += g_deg[i]; }
    if (t == 1023) g_row[N_NODES] = partial[1023];
}

__global__ void k_place_self() {
    int i = blockIdx.x * blockDim.x + threadIdx.x;
    if (i < N_NODES) {
        int p = g_row[i];
        g_csrc[p] = i;
        g_cur[i] = p + 1;
    }
}

__global__ void k_scatter(const int* __restrict__ ei) {
    int e = blockIdx.x * blockDim.x + threadIdx.x;
    if (e < N_EDGES) {
        int d = ei[N_EDGES + e];
        int s = ei[e];
        int p = atomicAdd(&g_cur[d], 1);
        g_csrc[p] = s;
    }
}

// ---------------- tf32 tensor-core GEMM: H[M,96] = A[M,K] @ W[K,96] --------
// block tile 128x96, 512 threads = 16 warps (4 m-warps x 4 n-warps).
// warp tile 32x24 = 2x3 mma.m16n8k8 tiles. fp32->tf32 cvt.rna at fill.
__device__ __forceinline__ uint32_t f2tf(float f) {
    uint32_t r;
    asm("cvt.rna.tf32.f32 %0, %1;" : "=r"(r) : "f"(f));
    return r;
}

template <int K, bool FROMBUF>
__global__ void __launch_bounds__(512) k_gemm(const float* __restrict__ Ain,
                                              const float* __restrict__ W) {
    __shared__ uint32_t As[32][136];   // [k][m], pad 136 (≡8 mod 32: conflict-free)
    __shared__ uint32_t Bs[32][104];   // [k][n], pad 104
    const float* A = FROMBUF ? g_buf : Ain;
    const int tid  = threadIdx.x;
    const int lane = tid & 31;
    const int warp = tid >> 5;
    const int wm   = warp >> 2;        // 0..3  (m block of 32)
    const int wn   = warp & 3;         // 0..3  (n block of 24)
    const int gid  = lane >> 2;        // 0..7
    const int tig  = lane & 3;         // 0..3
    const int m0   = blockIdx.x * 128;
    const int NCH  = K / 32;

    float acc[2][3][4];
#pragma unroll
    for (int tm = 0; tm < 2; tm++)
#pragma unroll
        for (int tn = 0; tn < 3; tn++)
#pragma unroll
            for (int i = 0; i < 4; i++) acc[tm][tn][i] = 0.f;

    uint32_t pA[8], pB[6];
    // prefetch chunk 0
#pragma unroll
    for (int i = 0; i < 8; i++) {
        int idx = tid + i * 512;
        int k = idx & 31, m = idx >> 5;
        int row = m0 + m;
        pA[i] = f2tf((row < N_NODES) ? A[row * K + k] : 0.f);
    }
#pragma unroll
    for (int i = 0; i < 6; i++) {
        int idx = tid + i * 512;
        int c = idx % 96, k = idx / 96;
        pB[i] = f2tf(W[k * 96 + c]);
    }

#pragma unroll
    for (int ch = 0; ch < NCH; ch++) {
#pragma unroll
        for (int i = 0; i < 8; i++) {
            int idx = tid + i * 512;
            int k = idx & 31, m = idx >> 5;
            As[k][m] = pA[i];
        }
#pragma unroll
        for (int i = 0; i < 6; i++) {
            int idx = tid + i * 512;
            int c = idx % 96, k = idx / 96;
            Bs[k][c] = pB[i];
        }
        __syncthreads();

        if (ch + 1 < NCH) {
            int k0 = (ch + 1) * 32;
#pragma unroll
            for (int i = 0; i < 8; i++) {
                int idx = tid + i * 512;
                int k = idx & 31, m = idx >> 5;
                int row = m0 + m;
                pA[i] = f2tf((row < N_NODES) ? A[row * K + k0 + k] : 0.f);
            }
#pragma unroll
            for (int i = 0; i < 6; i++) {
                int idx = tid + i * 512;
                int c = idx % 96, k = idx / 96;
                pB[i] = f2tf(W[(k0 + k) * 96 + c]);
            }
        }

#pragma unroll
        for (int k8 = 0; k8 < 4; k8++) {
            const int kb = k8 * 8;
            uint32_t af[2][4];
#pragma unroll
            for (int tm = 0; tm < 2; tm++) {
                int mb = wm * 32 + tm * 16;
                af[tm][0] = As[kb + tig][mb + gid];
                af[tm][1] = As[kb + tig][mb + gid + 8];
                af[tm][2] = As[kb + tig + 4][mb + gid];
                af[tm][3] = As[kb + tig + 4][mb + gid + 8];
            }
            uint32_t bf[3][2];
#pragma unroll
            for (int tn = 0; tn < 3; tn++) {
                int nb = wn * 24 + tn * 8;
                bf[tn][0] = Bs[kb + tig][nb + gid];
                bf[tn][1] = Bs[kb + tig + 4][nb + gid];
            }
#pragma unroll
            for (int tm = 0; tm < 2; tm++)
#pragma unroll
                for (int tn = 0; tn < 3; tn++) {
                    asm volatile(
                        "mma.sync.aligned.m16n8k8.row.col.f32.tf32.tf32.f32 "
                        "{%0,%1,%2,%3}, {%4,%5,%6,%7}, {%8,%9}, {%0,%1,%2,%3};"
                        : "+f"(acc[tm][tn][0]), "+f"(acc[tm][tn][1]),
                          "+f"(acc[tm][tn][2]), "+f"(acc[tm][tn][3])
                        : "r"(af[tm][0]), "r"(af[tm][1]),
                          "r"(af[tm][2]), "r"(af[tm][3]),
                          "r"(bf[tn][0]), "r"(bf[tn][1]));
                }
        }
        __syncthreads();
    }

    // epilogue: D fragment c0,c1 at (gid, 2*tig..+1), c2,c3 at (gid+8, ...)
#pragma unroll
    for (int tm = 0; tm < 2; tm++) {
        int rbase = m0 + wm * 32 + tm * 16;
        int row0 = rbase + gid;
        int row1 = rbase + gid + 8;
#pragma unroll
        for (int tn = 0; tn < 3; tn++) {
            int col = wn * 24 + tn * 8 + 2 * tig;
            if (row0 < N_NODES) {
                float2 v = make_float2(acc[tm][tn][0], acc[tm][tn][1]);
                *(float2*)&g_h[row0 * 96 + col] = v;
            }
            if (row1 < N_NODES) {
                float2 v = make_float2(acc[tm][tn][2], acc[tm][tn][3]);
                *(float2*)&g_h[row1 * 96 + col] = v;
            }
        }
    }
}

// ---------------- per-node attention logits ----------------
__global__ void k_alpha(const float* __restrict__ asrc, const float* __restrict__ adst) {
    int warp = (blockIdx.x * blockDim.x + threadIdx.x) >> 5;
    int lane = threadIdx.x & 31;
    if (warp >= N_NODES) return;
    float s1 = 0.f, s2 = 0.f;
#pragma unroll
    for (int i = 0; i < 3; i++) {
        float v = g_h[warp * 96 + lane + 32 * i];
        s1 = fmaf(v, asrc[lane + 32 * i], s1);
        s2 = fmaf(v, adst[lane + 32 * i], s2);
    }
#pragma unroll
    for (int o = 16; o; o >>= 1) {
        s1 += __shfl_xor_sync(0xffffffffu, s1, o);
        s2 += __shfl_xor_sync(0xffffffffu, s2, o);
    }
    if (lane == 0) { g_as[warp] = s1; g_ad[warp] = s2; }
}

// ---------------- warp-per-dst softmax + aggregation, single pass ----------
__global__ void k_agg(const float* __restrict__ bias, int act) {
    int d    = (blockIdx.x * blockDim.x + threadIdx.x) >> 5;
    int lane = threadIdx.x & 31;
    if (d >= N_NODES) return;
    const int start = g_row[d];
    const int end   = g_row[d + 1];
    const float ad  = g_ad[d];

    float denom = 0.f, a0 = 0.f, a1 = 0.f, a2 = 0.f;
    for (int base = start; base < end; base += 32) {
        int j = base + lane;
        int s = 0;
        float w = 0.f;
        if (j < end) {
            s = __ldg(&g_csrc[j]);
            float e = __ldg(&g_as[s]) + ad;
            e = e > 0.f ? e : 0.2f * e;
            w = __expf(e);
        }
        denom += w;
        const int cnt = min(32, end - base);
        int t = 0;
        for (; t + 2 <= cnt; t += 2) {
            float wt0 = __shfl_sync(0xffffffffu, w, t);
            int   st0 = __shfl_sync(0xffffffffu, s, t);
            float wt1 = __shfl_sync(0xffffffffu, w, t + 1);
            int   st1 = __shfl_sync(0xffffffffu, s, t + 1);
            const float* h0 = g_h + st0 * 96;
            const float* h1 = g_h + st1 * 96;
            float v00 = __ldg(h0 + lane), v01 = __ldg(h0 + lane + 32), v02 = __ldg(h0 + lane + 64);
            float v10 = __ldg(h1 + lane), v11 = __ldg(h1 + lane + 32), v12 = __ldg(h1 + lane + 64);
            a0 = fmaf(wt0, v00, a0); a1 = fmaf(wt0, v01, a1); a2 = fmaf(wt0, v02, a2);
            a0 = fmaf(wt1, v10, a0); a1 = fmaf(wt1, v11, a1); a2 = fmaf(wt1, v12, a2);
        }
        if (t < cnt) {
            float wt = __shfl_sync(0xffffffffu, w, t);
            int   st = __shfl_sync(0xffffffffu, s, t);
            const float* hp = g_h + st * 96;
            a0 = fmaf(wt, __ldg(hp + lane),      a0);
            a1 = fmaf(wt, __ldg(hp + lane + 32), a1);
            a2 = fmaf(wt, __ldg(hp + lane + 64), a2);
        }
    }
#pragma unroll
    for (int o = 16; o; o >>= 1) denom += __shfl_xor_sync(0xffffffffu, denom, o);
    float inv = 1.f / (denom + 1e-16f);

    float o0 = a0 * inv + bias[lane];
    float o1 = a1 * inv + bias[lane + 32];
    float o2 = a2 * inv + bias[lane + 64];
    if (act) {
        o0 = o0 > 0.f ? o0 : 0.01f * o0;
        o1 = o1 > 0.f ? o1 : 0.01f * o1;
        o2 = o2 > 0.f ? o2 : 0.01f * o2;
    }
    g_buf[d * 96 + lane]      = o0;
    g_buf[d * 96 + lane + 32] = o1;
    g_buf[d * 96 + lane + 64] = o2;
}

// ---------------- global mean pool (batch is sorted, int32) ----------------
__global__ void k_pool(const int* __restrict__ batch, float* __restrict__ out) {
    int g = blockIdx.x;
    __shared__ int s_lo, s_hi;
    if (threadIdx.x == 0) {
        int l = 0, r = N_NODES;
        while (l < r) { int mid = (l + r) >> 1; if (batch[mid] < g) l = mid + 1; else r = mid; }
        s_lo = l;
        l = 0; r = N_NODES;
        while (l < r) { int mid = (l + r) >> 1; if (batch[mid] < g + 1) l = mid + 1; else r = mid; }
        s_hi = l;
    }
    __syncthreads();
    int t = threadIdx.x;   // 96 threads
    float s = 0.f;
    for (int n = s_lo; n < s_hi; n++) s += g_buf[n * 96 + t];
    int cnt = s_hi - s_lo;
    out[g * 96 + t] = s / (float)max(cnt, 1);
}

// ---------------- launch ----------------
extern "C" void kernel_launch(void* const* d_in, const int* in_sizes, int n_in,
                              void* d_out, int out_size) {
    const float* x     = (const float*)d_in[0];
    const int*   ei    = (const int*)d_in[1];    // int32 (JAX x64 disabled)
    const int*   batch = (const int*)d_in[2];    // int32
    const float* W1 = (const float*)d_in[3];
    const float* s1 = (const float*)d_in[4];
    const float* a1 = (const float*)d_in[5];
    const float* b1 = (const float*)d_in[6];
    const float* W2 = (const float*)d_in[7];
    const float* s2 = (const float*)d_in[8];
    const float* a2 = (const float*)d_in[9];
    const float* b2 = (const float*)d_in[10];
    const float* W3 = (const float*)d_in[11];
    const float* s3 = (const float*)d_in[12];
    const float* a3 = (const float*)d_in[13];
    const float* b3 = (const float*)d_in[14];
    float* out = (float*)d_out;

    // lazily-created side stream + fork/join events (host resources only)
    static cudaStream_t sB = nullptr;
    static cudaEvent_t evFork = nullptr, evJoin = nullptr;
    if (sB == nullptr) {
        cudaStreamCreateWithFlags(&sB, cudaStreamNonBlocking);
        cudaEventCreateWithFlags(&evFork, cudaEventDisableTiming);
        cudaEventCreateWithFlags(&evJoin, cudaEventDisableTiming);
    }

    // ---- fork: CSR build on side stream, layer-1 GEMM+alpha on main ----
    cudaEventRecord(evFork, 0);
    cudaStreamWaitEvent(sB, evFork, 0);

    k_init_deg<<<(N_NODES + 255) / 256, 256, 0, sB>>>();
    k_count<<<(N_EDGES + 255) / 256, 256, 0, sB>>>(ei);
    k_scan<<<1, 1024, 0, sB>>>();
    k_place_self<<<(N_NODES + 255) / 256, 256, 0, sB>>>();
    k_scatter<<<(N_EDGES + 255) / 256, 256, 0, sB>>>(ei);
    cudaEventRecord(evJoin, sB);

    const int GEMM_GRID = (N_NODES + 127) / 128;
    const int WARP_GRID = (N_NODES * 32 + 255) / 256;

    k_gemm<DIM_IN, false><<<GEMM_GRID, 512>>>(x, W1);
    k_alpha<<<WARP_GRID, 256>>>(s1, a1);

    // ---- join: aggregation needs both CSR and alpha ----
    cudaStreamWaitEvent(0, evJoin, 0);
    k_agg<<<WARP_GRID, 256>>>(b1, 1);

    // layer 2
    k_gemm<DIM, true><<<GEMM_GRID, 512>>>(nullptr, W2);
    k_alpha<<<WARP_GRID, 256>>>(s2, a2);
    k_agg<<<WARP_GRID, 256>>>(b2, 1);
    // layer 3
    k_gemm<DIM, true><<<GEMM_GRID, 512>>>(nullptr, W3);
    k_alpha<<<WARP_GRID, 256>>>(s3, a3);
    k_agg<<<WARP_GRID, 256>>>(b3, 0);

    // pool
    k_pool<<<NUM_GRAPHS, 96>>>(batch, out);
}

// round 15
// speedup vs baseline: 1.2348x; 1.0069x over previous
#include <cuda_runtime.h>
#include <math.h>
#include <stdint.h>

#define N_NODES 50000
#define N_EDGES 800000
#define ETOT (N_EDGES + N_NODES)
#define DIM_IN 128
#define DIM 96
#define NUM_GRAPHS 64

// ---------------- scratch (device globals) ----------
__device__ float g_h[N_NODES * DIM];     // post-GEMM features
__device__ float g_buf[N_NODES * DIM];   // post-aggregation layer output
__device__ float g_as[N_NODES];          // alpha_src per node
__device__ float g_ad[N_NODES];          // alpha_dst per node
__device__ int   g_deg[N_NODES];
__device__ int   g_row[N_NODES + 1];
__device__ int   g_cur[N_NODES];
__device__ int   g_csrc[ETOT];           // CSR (by dst) source node ids

// ---------------- CSR build (5 small kernels — measured-fast structure) ----
__global__ void k_init_deg() {
    int i = blockIdx.x * blockDim.x + threadIdx.x;
    if (i < N_NODES) g_deg[i] = 1;   // self loop
}

__global__ void k_count(const int* __restrict__ ei) {
    int e = blockIdx.x * blockDim.x + threadIdx.x;
    if (e < N_EDGES) atomicAdd(&g_deg[ei[N_EDGES + e]], 1);
}

__global__ void k_scan() {
    __shared__ int partial[1024];
    const int t = threadIdx.x;
    const int CH = (N_NODES + 1023) / 1024;
    int b = t * CH;
    int e = min(b + CH, N_NODES);
    int s = 0;
    for (int i = b; i < e; i++) s += g_deg[i];
    partial[t] = s;
    __syncthreads();
    for (int off = 1; off < 1024; off <<= 1) {
        int add = (t >= off) ? partial[t - off] : 0;
        __syncthreads();
        partial[t] += add;
        __syncthreads();
    }
    int run = (t > 0) ? partial[t - 1] : 0;
    for (int i = b; i < e; i++) { g_row[i] = run; run += g_deg[i]; }
    if (t == 1023) g_row[N_NODES] = partial[1023];
}

__global__ void k_place_self() {
    int i = blockIdx.x * blockDim.x + threadIdx.x;
    if (i < N_NODES) {
        int p = g_row[i];
        g_csrc[p] = i;
        g_cur[i] = p + 1;
    }
}

__global__ void k_scatter(const int* __restrict__ ei) {
    int e = blockIdx.x * blockDim.x + threadIdx.x;
    if (e < N_EDGES) {
        int d = ei[N_EDGES + e];
        int s = ei[e];
        int p = atomicAdd(&g_cur[d], 1);
        g_csrc[p] = s;
    }
}

// ---------------- tf32 tensor-core GEMM + fused alpha ----------------------
// block tile 128x96, 512 threads = 16 warps (4 m-warps x 4 n-warps).
// warp tile 32x24 = 2x3 mma.m16n8k8. Epilogue also computes
// as/ad = H·asrc / H·adst per row: 2 shfl + smem atomics (no shuffle trees).
__device__ __forceinline__ uint32_t f2tf(float f) {
    uint32_t r;
    asm("cvt.rna.tf32.f32 %0, %1;" : "=r"(r) : "f"(f));
    return r;
}

template <int K, bool FROMBUF>
__global__ void __launch_bounds__(512) k_gemm(const float* __restrict__ Ain,
                                              const float* __restrict__ W,
                                              const float* __restrict__ asrc,
                                              const float* __restrict__ adst) {
    __shared__ uint32_t As[32][136];   // [k][m], pad ≡8 mod 32: conflict-free
    __shared__ uint32_t Bs[32][104];   // [k][n]
    __shared__ float sAs[128], sAd[128];
    const float* A = FROMBUF ? g_buf : Ain;
    const int tid  = threadIdx.x;
    const int lane = tid & 31;
    const int warp = tid >> 5;
    const int wm   = warp >> 2;        // 0..3  (m block of 32)
    const int wn   = warp & 3;         // 0..3  (n block of 24)
    const int gid  = lane >> 2;        // 0..7
    const int tig  = lane & 3;         // 0..3
    const int m0   = blockIdx.x * 128;
    const int NCH  = K / 32;

    if (tid < 128) { sAs[tid] = 0.f; sAd[tid] = 0.f; }

    float acc[2][3][4];
#pragma unroll
    for (int tm = 0; tm < 2; tm++)
#pragma unroll
        for (int tn = 0; tn < 3; tn++)
#pragma unroll
            for (int i = 0; i < 4; i++) acc[tm][tn][i] = 0.f;

    uint32_t pA[8], pB[6];
#pragma unroll
    for (int i = 0; i < 8; i++) {
        int idx = tid + i * 512;
        int k = idx & 31, m = idx >> 5;
        int row = m0 + m;
        pA[i] = f2tf((row < N_NODES) ? A[row * K + k] : 0.f);
    }
#pragma unroll
    for (int i = 0; i < 6; i++) {
        int idx = tid + i * 512;
        int c = idx % 96, k = idx / 96;
        pB[i] = f2tf(W[k * 96 + c]);
    }

#pragma unroll
    for (int ch = 0; ch < NCH; ch++) {
#pragma unroll
        for (int i = 0; i < 8; i++) {
            int idx = tid + i * 512;
            int k = idx & 31, m = idx >> 5;
            As[k][m] = pA[i];
        }
#pragma unroll
        for (int i = 0; i < 6; i++) {
            int idx = tid + i * 512;
            int c = idx % 96, k = idx / 96;
            Bs[k][c] = pB[i];
        }
        __syncthreads();

        if (ch + 1 < NCH) {
            int k0 = (ch + 1) * 32;
#pragma unroll
            for (int i = 0; i < 8; i++) {
                int idx = tid + i * 512;
                int k = idx & 31, m = idx >> 5;
                int row = m0 + m;
                pA[i] = f2tf((row < N_NODES) ? A[row * K + k0 + k] : 0.f);
            }
#pragma unroll
            for (int i = 0; i < 6; i++) {
                int idx = tid + i * 512;
                int c = idx % 96, k = idx / 96;
                pB[i] = f2tf(W[(k0 + k) * 96 + c]);
            }
        }

#pragma unroll
        for (int k8 = 0; k8 < 4; k8++) {
            const int kb = k8 * 8;
            uint32_t af[2][4];
#pragma unroll
            for (int tm = 0; tm < 2; tm++) {
                int mb = wm * 32 + tm * 16;
                af[tm][0] = As[kb + tig][mb + gid];
                af[tm][1] = As[kb + tig][mb + gid + 8];
                af[tm][2] = As[kb + tig + 4][mb + gid];
                af[tm][3] = As[kb + tig + 4][mb + gid + 8];
            }
            uint32_t bf[3][2];
#pragma unroll
            for (int tn = 0; tn < 3; tn++) {
                int nb = wn * 24 + tn * 8;
                bf[tn][0] = Bs[kb + tig][nb + gid];
                bf[tn][1] = Bs[kb + tig + 4][nb + gid];
            }
#pragma unroll
            for (int tm = 0; tm < 2; tm++)
#pragma unroll
                for (int tn = 0; tn < 3; tn++) {
                    asm volatile(
                        "mma.sync.aligned.m16n8k8.row.col.f32.tf32.tf32.f32 "
                        "{%0,%1,%2,%3}, {%4,%5,%6,%7}, {%8,%9}, {%0,%1,%2,%3};"
                        : "+f"(acc[tm][tn][0]), "+f"(acc[tm][tn][1]),
                          "+f"(acc[tm][tn][2]), "+f"(acc[tm][tn][3])
                        : "r"(af[tm][0]), "r"(af[tm][1]),
                          "r"(af[tm][2]), "r"(af[tm][3]),
                          "r"(bf[tn][0]), "r"(bf[tn][1]));
                }
        }
        __syncthreads();
    }

    // attention-coefficient values for this thread's 6 columns
    float cs[3][2], cd[3][2];
#pragma unroll
    for (int tn = 0; tn < 3; tn++) {
        int col = wn * 24 + tn * 8 + 2 * tig;
        cs[tn][0] = __ldg(&asrc[col]);     cs[tn][1] = __ldg(&asrc[col + 1]);
        cd[tn][0] = __ldg(&adst[col]);     cd[tn][1] = __ldg(&adst[col + 1]);
    }

    // epilogue: store h + accumulate alpha partials
#pragma unroll
    for (int tm = 0; tm < 2; tm++) {
        int lbase = wm * 32 + tm * 16;
        int row0 = m0 + lbase + gid;
        int row1 = m0 + lbase + gid + 8;
        float ps0 = 0.f, pd0 = 0.f, ps1 = 0.f, pd1 = 0.f;
#pragma unroll
        for (int tn = 0; tn < 3; tn++) {
            int col = wn * 24 + tn * 8 + 2 * tig;
            ps0 = fmaf(acc[tm][tn][0], cs[tn][0], ps0);
            ps0 = fmaf(acc[tm][tn][1], cs[tn][1], ps0);
            pd0 = fmaf(acc[tm][tn][0], cd[tn][0], pd0);
            pd0 = fmaf(acc[tm][tn][1], cd[tn][1], pd0);
            ps1 = fmaf(acc[tm][tn][2], cs[tn][0], ps1);
            ps1 = fmaf(acc[tm][tn][3], cs[tn][1], ps1);
            pd1 = fmaf(acc[tm][tn][2], cd[tn][0], pd1);
            pd1 = fmaf(acc[tm][tn][3], cd[tn][1], pd1);
            if (row0 < N_NODES) {
                float2 v = make_float2(acc[tm][tn][0], acc[tm][tn][1]);
                *(float2*)&g_h[row0 * 96 + col] = v;
            }
            if (row1 < N_NODES) {
                float2 v = make_float2(acc[tm][tn][2], acc[tm][tn][3]);
                *(float2*)&g_h[row1 * 96 + col] = v;
            }
        }
        // reduce over the 4 tig lanes (xor 1, 2), then one lane commits
#pragma unroll
        for (int o = 1; o <= 2; o <<= 1) {
            ps0 += __shfl_xor_sync(0xffffffffu, ps0, o);
            pd0 += __shfl_xor_sync(0xffffffffu, pd0, o);
            ps1 += __shfl_xor_sync(0xffffffffu, ps1, o);
            pd1 += __shfl_xor_sync(0xffffffffu, pd1, o);
        }
        if (tig == 0) {
            atomicAdd(&sAs[lbase + gid],     ps0);
            atomicAdd(&sAd[lbase + gid],     pd0);
            atomicAdd(&sAs[lbase + gid + 8], ps1);
            atomicAdd(&sAd[lbase + gid + 8], pd1);
        }
    }
    __syncthreads();
    if (tid < 128) {
        int row = m0 + tid;
        if (row < N_NODES) {
            g_as[row] = sAs[tid];
            g_ad[row] = sAd[tid];
        }
    }
}

// ---------------- warp-per-dst softmax + aggregation, single pass ----------
__global__ void k_agg(const float* __restrict__ bias, int act) {
    int d    = (blockIdx.x * blockDim.x + threadIdx.x) >> 5;
    int lane = threadIdx.x & 31;
    if (d >= N_NODES) return;
    const int start = g_row[d];
    const int end   = g_row[d + 1];
    const float ad  = g_ad[d];

    float denom = 0.f, a0 = 0.f, a1 = 0.f, a2 = 0.f;
    for (int base = start; base < end; base += 32) {
        int j = base + lane;
        int s = 0;
        float w = 0.f;
        if (j < end) {
            s = __ldg(&g_csrc[j]);
            float e = __ldg(&g_as[s]) + ad;
            e = e > 0.f ? e : 0.2f * e;
            w = __expf(e);
        }
        denom += w;
        const int cnt = min(32, end - base);
        int t = 0;
        for (; t + 2 <= cnt; t += 2) {
            float wt0 = __shfl_sync(0xffffffffu, w, t);
            int   st0 = __shfl_sync(0xffffffffu, s, t);
            float wt1 = __shfl_sync(0xffffffffu, w, t + 1);
            int   st1 = __shfl_sync(0xffffffffu, s, t + 1);
            const float* h0 = g_h + st0 * 96;
            const float* h1 = g_h + st1 * 96;
            float v00 = __ldg(h0 + lane), v01 = __ldg(h0 + lane + 32), v02 = __ldg(h0 + lane + 64);
            float v10 = __ldg(h1 + lane), v11 = __ldg(h1 + lane + 32), v12 = __ldg(h1 + lane + 64);
            a0 = fmaf(wt0, v00, a0); a1 = fmaf(wt0, v01, a1); a2 = fmaf(wt0, v02, a2);
            a0 = fmaf(wt1, v10, a0); a1 = fmaf(wt1, v11, a1); a2 = fmaf(wt1, v12, a2);
        }
        if (t < cnt) {
            float wt = __shfl_sync(0xffffffffu, w, t);
            int   st = __shfl_sync(0xffffffffu, s, t);
            const float* hp = g_h + st * 96;
            a0 = fmaf(wt, __ldg(hp + lane),      a0);
            a1 = fmaf(wt, __ldg(hp + lane + 32), a1);
            a2 = fmaf(wt, __ldg(hp + lane + 64), a2);
        }
    }
#pragma unroll
    for (int o = 16; o; o >>= 1) denom += __shfl_xor_sync(0xffffffffu, denom, o);
    float inv = 1.f / (denom + 1e-16f);

    float o0 = a0 * inv + __ldg(&bias[lane]);
    float o1 = a1 * inv + __ldg(&bias[lane + 32]);
    float o2 = a2 * inv + __ldg(&bias[lane + 64]);
    if (act) {
        o0 = o0 > 0.f ? o0 : 0.01f * o0;
        o1 = o1 > 0.f ? o1 : 0.01f * o1;
        o2 = o2 > 0.f ? o2 : 0.01f * o2;
    }
    g_buf[d * 96 + lane]      = o0;
    g_buf[d * 96 + lane + 32] = o1;
    g_buf[d * 96 + lane + 64] = o2;
}

// ---------------- global mean pool (batch is sorted, int32) ----------------
__global__ void k_pool(const int* __restrict__ batch, float* __restrict__ out) {
    int g = blockIdx.x;
    __shared__ int s_lo, s_hi;
    if (threadIdx.x == 0) {
        int l = 0, r = N_NODES;
        while (l < r) { int mid = (l + r) >> 1; if (batch[mid] < g) l = mid + 1; else r = mid; }
        s_lo = l;
        l = 0; r = N_NODES;
        while (l < r) { int mid = (l + r) >> 1; if (batch[mid] < g + 1) l = mid + 1; else r = mid; }
        s_hi = l;
    }
    __syncthreads();
    int t = threadIdx.x;   // 96 threads
    float s = 0.f;
    for (int n = s_lo; n < s_hi; n++) s += g_buf[n * 96 + t];
    int cnt = s_hi - s_lo;
    out[g * 96 + t] = s / (float)max(cnt, 1);
}

// ---------------- launch ----------------
extern "C" void kernel_launch(void* const* d_in, const int* in_sizes, int n_in,
                              void* d_out, int out_size) {
    const float* x     = (const float*)d_in[0];
    const int*   ei    = (const int*)d_in[1];    // int32 (JAX x64 disabled)
    const int*   batch = (const int*)d_in[2];    // int32
    const float* W1 = (const float*)d_in[3];
    const float* s1 = (const float*)d_in[4];
    const float* a1 = (const float*)d_in[5];
    const float* b1 = (const float*)d_in[6];
    const float* W2 = (const float*)d_in[7];
    const float* s2 = (const float*)d_in[8];
    const float* a2 = (const float*)d_in[9];
    const float* b2 = (const float*)d_in[10];
    const float* W3 = (const float*)d_in[11];
    const float* s3 = (const float*)d_in[12];
    const float* a3 = (const float*)d_in[13];
    const float* b3 = (const float*)d_in[14];
    float* out = (float*)d_out;

    // lazily-created side stream + fork/join events (host resources only)
    static cudaStream_t sB = nullptr;
    static cudaEvent_t evFork = nullptr, evJoin = nullptr;
    if (sB == nullptr) {
        cudaStreamCreateWithFlags(&sB, cudaStreamNonBlocking);
        cudaEventCreateWithFlags(&evFork, cudaEventDisableTiming);
        cudaEventCreateWithFlags(&evJoin, cudaEventDisableTiming);
    }

    // ---- fork: CSR build on side stream, layer-1 GEMM(+alpha) on main ----
    cudaEventRecord(evFork, 0);
    cudaStreamWaitEvent(sB, evFork, 0);

    k_init_deg<<<(N_NODES + 255) / 256, 256, 0, sB>>>();
    k_count<<<(N_EDGES + 255) / 256, 256, 0, sB>>>(ei);
    k_scan<<<1, 1024, 0, sB>>>();
    k_place_self<<<(N_NODES + 255) / 256, 256, 0, sB>>>();
    k_scatter<<<(N_EDGES + 255) / 256, 256, 0, sB>>>(ei);
    cudaEventRecord(evJoin, sB);

    const int GEMM_GRID = (N_NODES + 127) / 128;
    const int WARP_GRID = (N_NODES * 32 + 255) / 256;

    k_gemm<DIM_IN, false><<<GEMM_GRID, 512>>>(x, W1, s1, a1);

    // ---- join: aggregation needs both CSR and alpha ----
    cudaStreamWaitEvent(0, evJoin, 0);
    k_agg<<<WARP_GRID, 256>>>(b1, 1);

    // layer 2
    k_gemm<DIM, true><<<GEMM_GRID, 512>>>(nullptr, W2, s2, a2);
    k_agg<<<WARP_GRID, 256>>>(b2, 1);
    // layer 3
    k_gemm<DIM, true><<<GEMM_GRID, 512>>>(nullptr, W3, s3, a3);
    k_agg<<<WARP_GRID, 256>>>(b3, 0);

    // pool
    k_pool<<<NUM_GRAPHS, 96>>>(batch, out);
}